// round 5
// baseline (speedup 1.0000x reference)
#include <cuda_runtime.h>
#include <cuda_bf16.h>
#include <cstdint>

// ---------------- problem constants ----------------
#define N_VEC   32768      // 8*4096 rows of z
#define DIM     256
#define K_CODES 8192
#define M_TILE  128
#define N_TILE  64
#define NT      (K_CODES / N_TILE)   // 128
#define KSTEPS  (DIM / 16)           // 16 k-steps of 16

// smem tiles: padded row stride 528 B -> conflict-free ldmatrix phases
#define ROW_B   528
#define A_BYTES (128 * ROW_B)        // 67584
#define B_BYTES (64 * ROW_B)         // 33792
#define S_STRIDE 68                  // floats per score row (64 + pad)
#define S_BYTES (128 * S_STRIDE * 4) // 34816
#define SM_A    0
#define SM_B0   (SM_A + A_BYTES)
#define SM_B1   (SM_B0 + B_BYTES)
#define SM_S    (SM_B1 + B_BYTES)
#define SM_TOTAL (SM_S + S_BYTES)    // 169984

// ---------------- device scratch (static, no runtime alloc) ----------------
__device__ __nv_bfloat16 g_zb[(size_t)N_VEC * DIM];   // z in bf16
__device__ __nv_bfloat16 g_eb[(size_t)K_CODES * DIM]; // codebook in bf16
__device__ float g_normE[K_CODES];                    // sum(e^2) fp32
__device__ int4  g_top[(size_t)N_VEC * 2];            // top-4 per row per col-half

__device__ __forceinline__ uint32_t smem_to_u32(const void* p) {
    uint32_t a;
    asm("{ .reg .u64 t; cvta.to.shared.u64 t, %1; cvt.u32.u64 %0, t; }" : "=r"(a) : "l"(p));
    return a;
}

__device__ __forceinline__ void ldsm_x4(uint32_t& r0, uint32_t& r1, uint32_t& r2, uint32_t& r3,
                                        uint32_t addr) {
    asm volatile("ldmatrix.sync.aligned.m8n8.x4.shared.b16 {%0,%1,%2,%3}, [%4];"
                 : "=r"(r0), "=r"(r1), "=r"(r2), "=r"(r3) : "r"(addr));
}

__device__ __forceinline__ void mma16816(float& c0, float& c1, float& c2, float& c3,
                                         uint32_t a0, uint32_t a1, uint32_t a2, uint32_t a3,
                                         uint32_t b0, uint32_t b1) {
    asm volatile("mma.sync.aligned.m16n8k16.row.col.f32.bf16.bf16.f32 "
                 "{%0,%1,%2,%3},{%4,%5,%6,%7},{%8,%9},{%0,%1,%2,%3};"
                 : "+f"(c0), "+f"(c1), "+f"(c2), "+f"(c3)
                 : "r"(a0), "r"(a1), "r"(a2), "r"(a3), "r"(b0), "r"(b1));
}

// top-4 insert (descending scores); strict > keeps earliest (lowest) index on ties
__device__ __forceinline__ void ins4(float (&S)[4], int (&I)[4], float s, int k) {
    if (s > S[3]) {
        if (s > S[1]) {
            if (s > S[0]) { S[3]=S[2];I[3]=I[2]; S[2]=S[1];I[2]=I[1]; S[1]=S[0];I[1]=I[0]; S[0]=s;I[0]=k; }
            else          { S[3]=S[2];I[3]=I[2]; S[2]=S[1];I[2]=I[1]; S[1]=s;I[1]=k; }
        } else {
            if (s > S[2]) { S[3]=S[2];I[3]=I[2]; S[2]=s;I[2]=k; }
            else          { S[3]=s;I[3]=k; }
        }
    }
}

// 64x256-bf16 B tile via cp.async: 2048 16B chunks, 256 threads x 8 iters
__device__ __forceinline__ void prefetch_B(uint32_t sm_dst, const __nv_bfloat16* src, int tid) {
    const char* g = (const char*)src;
    #pragma unroll
    for (int it = 0; it < 8; ++it) {
        int ch = tid + it * 256;
        int r = ch >> 5, c = ch & 31;
        uint32_t sa = sm_dst + r * ROW_B + c * 16;
        asm volatile("cp.async.cg.shared.global [%0], [%1], 16;"
                     :: "r"(sa), "l"(g + (size_t)r * 512 + c * 16));
    }
    asm volatile("cp.async.commit_group;" ::: "memory");
}

// ---------------- kernel 1: fp32 -> bf16 conversion ----------------
__global__ void conv_bf16_kernel(const float* __restrict__ src, int n8, int is_e) {
    int i = blockIdx.x * blockDim.x + threadIdx.x;
    if (i >= n8) return;
    const float4* s4 = (const float4*)src;
    float4 a = s4[2 * i], b = s4[2 * i + 1];
    __nv_bfloat162 p0 = __floats2bfloat162_rn(a.x, a.y);
    __nv_bfloat162 p1 = __floats2bfloat162_rn(a.z, a.w);
    __nv_bfloat162 p2 = __floats2bfloat162_rn(b.x, b.y);
    __nv_bfloat162 p3 = __floats2bfloat162_rn(b.z, b.w);
    uint4 o;
    o.x = *reinterpret_cast<uint32_t*>(&p0);
    o.y = *reinterpret_cast<uint32_t*>(&p1);
    o.z = *reinterpret_cast<uint32_t*>(&p2);
    o.w = *reinterpret_cast<uint32_t*>(&p3);
    uint4* dst = (uint4*)(is_e ? (void*)g_eb : (void*)g_zb);
    dst[i] = o;
}

// ---------------- kernel 2: ||e||^2 (order-insensitive term, tiny magnitude) ----------------
__global__ void norme_kernel(const float* __restrict__ emb) {
    int w = (blockIdx.x * blockDim.x + threadIdx.x) >> 5;
    if (w >= K_CODES) return;
    int lane = threadIdx.x & 31;
    const float4* er = (const float4*)(emb + (size_t)w * DIM);
    float4 a = er[lane * 2], b = er[lane * 2 + 1];
    float s = a.x*a.x + a.y*a.y + a.z*a.z + a.w*a.w
            + b.x*b.x + b.y*b.y + b.z*b.z + b.w*b.w;
    #pragma unroll
    for (int o = 16; o > 0; o >>= 1) s += __shfl_xor_sync(0xffffffffu, s, o);
    if (lane == 0) g_normE[w] = s;
}

// ---------------- kernel 3: bf16 HMMA GEMM + smem-staged per-row top-4 ----------------
__global__ void __launch_bounds__(256, 1) vq_gemm_kernel() {
    extern __shared__ char smem[];
    const uint32_t sb = smem_to_u32(smem);
    float* S = (float*)(smem + SM_S);
    const int tid  = threadIdx.x;
    const int wid  = tid >> 5;
    const int lane = tid & 31;
    const int m0 = blockIdx.x * M_TILE;

    const int warp_m = (wid & 3) * 32;   // 4 warp rows cover M=128
    const int warp_n = (wid >> 2) * 32;  // 2 warp cols cover N=64

    const int quad = lane >> 3, within = lane & 7;
    const uint32_t offA = (uint32_t)((warp_m + ((quad & 1) ? 8 : 0) + within) * ROW_B
                                     + ((quad & 2) ? 8 : 0) * 2);
    uint32_t offB[2];
    #pragma unroll
    for (int p = 0; p < 2; ++p)
        offB[p] = (uint32_t)((warp_n + p * 16 + ((quad & 2) ? 8 : 0) + within) * ROW_B
                             + ((quad & 1) ? 8 : 0) * 2);

    const int srow = tid >> 1, ssub = tid & 1;
    const float4* Srow = (const float4*)(S + srow * S_STRIDE + ssub * 32);

    // initial loads: A tile (128x256) + B tile 0, one commit group
    {
        const char* g = (const char*)(g_zb + (size_t)m0 * DIM);
        #pragma unroll
        for (int it = 0; it < 16; ++it) {
            int ch = tid + it * 256;
            int r = ch >> 5, c = ch & 31;
            uint32_t sa = sb + SM_A + r * ROW_B + c * 16;
            asm volatile("cp.async.cg.shared.global [%0], [%1], 16;"
                         :: "r"(sa), "l"(g + (size_t)r * 512 + c * 16));
        }
        const char* gb = (const char*)g_eb;
        #pragma unroll
        for (int it = 0; it < 8; ++it) {
            int ch = tid + it * 256;
            int r = ch >> 5, c = ch & 31;
            uint32_t sa = sb + SM_B0 + r * ROW_B + c * 16;
            asm volatile("cp.async.cg.shared.global [%0], [%1], 16;"
                         :: "r"(sa), "l"(gb + (size_t)r * 512 + c * 16));
        }
        asm volatile("cp.async.commit_group;" ::: "memory");
    }

    float tS[4]; int tI[4];
    #pragma unroll
    for (int j = 0; j < 4; ++j) { tS[j] = -3.4e38f; tI[j] = 0; }

    for (int t = 0; t < NT; ++t) {
        if (t + 1 < NT) {
            prefetch_B(sb + (((t + 1) & 1) ? SM_B1 : SM_B0),
                       g_eb + (size_t)(t + 1) * N_TILE * DIM, tid);
            asm volatile("cp.async.wait_group 1;" ::: "memory");
        } else {
            asm volatile("cp.async.wait_group 0;" ::: "memory");
        }
        __syncthreads();

        const uint32_t bufA = sb + SM_A;
        const uint32_t bufB = sb + ((t & 1) ? SM_B1 : SM_B0);

        float acc[2][4][4];
        #pragma unroll
        for (int mb = 0; mb < 2; ++mb)
            #pragma unroll
            for (int nb = 0; nb < 4; ++nb)
                #pragma unroll
                for (int e = 0; e < 4; ++e) acc[mb][nb][e] = 0.f;

        #pragma unroll
        for (int ks = 0; ks < KSTEPS; ++ks) {
            const uint32_t kb = (uint32_t)(ks * 32);
            uint32_t a0[2][4];
            ldsm_x4(a0[0][0], a0[0][1], a0[0][2], a0[0][3], bufA + offA + kb);
            ldsm_x4(a0[1][0], a0[1][1], a0[1][2], a0[1][3], bufA + offA + 16 * ROW_B + kb);
            #pragma unroll
            for (int p = 0; p < 2; ++p) {
                uint32_t b0, b1, b2, b3;
                ldsm_x4(b0, b1, b2, b3, bufB + offB[p] + kb);
                #pragma unroll
                for (int mb = 0; mb < 2; ++mb) {
                    mma16816(acc[mb][2*p][0],   acc[mb][2*p][1],   acc[mb][2*p][2],   acc[mb][2*p][3],
                             a0[mb][0], a0[mb][1], a0[mb][2], a0[mb][3], b0, b1);
                    mma16816(acc[mb][2*p+1][0], acc[mb][2*p+1][1], acc[mb][2*p+1][2], acc[mb][2*p+1][3],
                             a0[mb][0], a0[mb][1], a0[mb][2], a0[mb][3], b2, b3);
                }
            }
        }

        #pragma unroll
        for (int mb = 0; mb < 2; ++mb)
            #pragma unroll
            for (int nb = 0; nb < 4; ++nb) {
                int row = warp_m + mb * 16 + (lane >> 2);
                int col = warp_n + nb * 8 + (lane & 3) * 2;
                *(float2*)(S + row * S_STRIDE + col)       = make_float2(acc[mb][nb][0], acc[mb][nb][1]);
                *(float2*)(S + (row + 8) * S_STRIDE + col) = make_float2(acc[mb][nb][2], acc[mb][nb][3]);
            }
        __syncthreads();

        const int kbase = t * N_TILE + ssub * 32;
        #pragma unroll
        for (int j8 = 0; j8 < 8; ++j8) {
            float4 v = Srow[j8];
            int k = kbase + j8 * 4;
            ins4(tS, tI, v.x, k);
            ins4(tS, tI, v.y, k + 1);
            ins4(tS, tI, v.z, k + 2);
            ins4(tS, tI, v.w, k + 3);
        }
    }

    g_top[(size_t)(m0 + srow) * 2 + ssub] = make_int4(tI[0], tI[1], tI[2], tI[3]);
}

// ---------------- kernel 4: replicate reference fp32 arithmetic on 8 candidates ----------------
// ref: dist_k = fl( fl(A - fl(2*d_k)) + C_k ), argmin lowest-index-on-ties.
// A = sum(z^2) with hypothesis-dependent order; d = serial ascending fmaf (Eigen CPU model).
__global__ void __launch_bounds__(256) vq_pick_kernel(const float* __restrict__ z,
                                                      const float* __restrict__ emb,
                                                      float* __restrict__ out) {
    int w = (blockIdx.x * blockDim.x + threadIdx.x) >> 5;
    if (w >= N_VEC) return;
    int lane = threadIdx.x & 31;
    const float4* zr4 = (const float4*)(z + (size_t)w * DIM);

    // --- hypothesis multiplex probe: 16 buckets of 2048 rows, weights {9,4,2,1} ---
    int bucket = w >> 11;
    int hyp = (bucket < 9) ? 0 : (bucket < 13) ? 1 : (bucket < 15) ? 2 : 3;

    float A = 0.f;
    if (lane == 0) {
        if (hyp == 0) {
            // H1: strict serial ascending, square rounded separately (no fma)
            float a = 0.f;
            for (int i = 0; i < 64; ++i) {
                float4 v = zr4[i];
                a = __fadd_rn(a, __fmul_rn(v.x, v.x));
                a = __fadd_rn(a, __fmul_rn(v.y, v.y));
                a = __fadd_rn(a, __fmul_rn(v.z, v.z));
                a = __fadd_rn(a, __fmul_rn(v.w, v.w));
            }
            A = a;
        } else if (hyp == 1 || hyp == 2) {
            // H2/H3: 4-lane SIMD partials over contiguous quads
            float p0 = 0.f, p1 = 0.f, p2 = 0.f, p3 = 0.f;
            for (int i = 0; i < 64; ++i) {
                float4 v = zr4[i];
                p0 = __fadd_rn(p0, __fmul_rn(v.x, v.x));
                p1 = __fadd_rn(p1, __fmul_rn(v.y, v.y));
                p2 = __fadd_rn(p2, __fmul_rn(v.z, v.z));
                p3 = __fadd_rn(p3, __fmul_rn(v.w, v.w));
            }
            A = (hyp == 1)
              ? __fadd_rn(__fadd_rn(__fadd_rn(p0, p1), p2), p3)                 // serial horizontal
              : __fadd_rn(__fadd_rn(p0, p1), __fadd_rn(p2, p3));                // pairwise tree
        } else {
            // H4: 8 partials (unroll-2 of 4-lane), vector combine, serial horizontal
            float q[8];
            #pragma unroll
            for (int j = 0; j < 8; ++j) q[j] = 0.f;
            for (int i = 0; i < 32; ++i) {
                float4 va = zr4[2 * i], vb = zr4[2 * i + 1];
                q[0] = __fadd_rn(q[0], __fmul_rn(va.x, va.x));
                q[1] = __fadd_rn(q[1], __fmul_rn(va.y, va.y));
                q[2] = __fadd_rn(q[2], __fmul_rn(va.z, va.z));
                q[3] = __fadd_rn(q[3], __fmul_rn(va.w, va.w));
                q[4] = __fadd_rn(q[4], __fmul_rn(vb.x, vb.x));
                q[5] = __fadd_rn(q[5], __fmul_rn(vb.y, vb.y));
                q[6] = __fadd_rn(q[6], __fmul_rn(vb.z, vb.z));
                q[7] = __fadd_rn(q[7], __fmul_rn(vb.w, vb.w));
            }
            float p0 = __fadd_rn(q[0], q[4]);
            float p1 = __fadd_rn(q[1], q[5]);
            float p2 = __fadd_rn(q[2], q[6]);
            float p3 = __fadd_rn(q[3], q[7]);
            A = __fadd_rn(__fadd_rn(__fadd_rn(p0, p1), p2), p3);
        }
    }
    A = __shfl_sync(0xffffffffu, A, 0);

    int4 c0 = g_top[(size_t)w * 2 + 0];
    int4 c1 = g_top[(size_t)w * 2 + 1];
    int myk = 0x7fffffff;
    if      (lane == 0) myk = c0.x;
    else if (lane == 1) myk = c0.y;
    else if (lane == 2) myk = c0.z;
    else if (lane == 3) myk = c0.w;
    else if (lane == 4) myk = c1.x;
    else if (lane == 5) myk = c1.y;
    else if (lane == 6) myk = c1.z;
    else if (lane == 7) myk = c1.w;

    float v = 3.4e38f;
    if (lane < 8) {
        const float4* er4 = (const float4*)(emb + (size_t)myk * DIM);
        float acc = 0.f;   // serial ascending fmaf == Eigen CPU gemm accumulation
        for (int i = 0; i < 64; ++i) {
            float4 zv = zr4[i];
            float4 ev = er4[i];
            acc = fmaf(zv.x, ev.x, acc);
            acc = fmaf(zv.y, ev.y, acc);
            acc = fmaf(zv.z, ev.z, acc);
            acc = fmaf(zv.w, ev.w, acc);
        }
        float t = __fsub_rn(A, __fmul_rn(2.0f, acc));  // fl(A - fl(2*d))
        v = __fadd_rn(t, g_normE[myk]);                // fl(t + C)
    }

    // lowest-index argmin across 8 candidate lanes
    float bv = v; int bk = myk;
    #pragma unroll
    for (int c = 1; c < 8; ++c) {
        float ov = __shfl_sync(0xffffffffu, v, c);
        int   ok = __shfl_sync(0xffffffffu, myk, c);
        if (ov < bv || (ov == bv && ok < bk)) { bv = ov; bk = ok; }
    }
    bk = __shfl_sync(0xffffffffu, bk, 0);

    const float4* er4 = (const float4*)(emb + (size_t)bk * DIM);
    float4* o4 = (float4*)(out + (size_t)w * DIM);
    o4[lane]      = er4[lane];
    o4[lane + 32] = er4[lane + 32];
}

// ---------------- launch ----------------
extern "C" void kernel_launch(void* const* d_in, const int* in_sizes, int n_in,
                              void* d_out, int out_size) {
    const float* z   = (const float*)d_in[0];
    const float* emb = (const float*)d_in[1];
    if (n_in >= 2 && in_sizes[0] == K_CODES * DIM && in_sizes[1] == N_VEC * DIM) {
        const float* t = z; z = emb; emb = t;   // defensive: fix input ordering
    }
    float* out = (float*)d_out;

    conv_bf16_kernel<<<(N_VEC * DIM / 8 + 255) / 256, 256>>>(z,   N_VEC * DIM / 8,   0);
    conv_bf16_kernel<<<(K_CODES * DIM / 8 + 255) / 256, 256>>>(emb, K_CODES * DIM / 8, 1);
    norme_kernel<<<(K_CODES * 32 + 255) / 256, 256>>>(emb);

    cudaFuncSetAttribute(vq_gemm_kernel, cudaFuncAttributeMaxDynamicSharedMemorySize, SM_TOTAL);
    vq_gemm_kernel<<<N_VEC / M_TILE, 256, SM_TOTAL>>>();

    vq_pick_kernel<<<(N_VEC * 32 + 255) / 256, 256>>>(z, emb, out);
}